// round 16
// baseline (speedup 1.0000x reference)
#include <cuda_runtime.h>
#include <cuda_bf16.h>
#include <cstdint>

#define B_ROWS 32768
#define K_DIM  512
#define N_DIM  2048
#define VBS    256
#define NVB    128

// ---------------- scratch (device globals; no allocations allowed) ----------
__device__ __align__(16) float g_Y[(size_t)B_ROWS * N_DIM];
__device__ __align__(16) float g_scale[NVB * N_DIM];
__device__ __align__(16) float g_shift[NVB * N_DIM];
__device__ __align__(16) __nv_bfloat16 g_Ahi[(size_t)B_ROWS * K_DIM];
__device__ __align__(16) __nv_bfloat16 g_Whi[(size_t)N_DIM * K_DIM];
__device__ __align__(16) signed char g_A8l[(size_t)B_ROWS * K_DIM];  // quant(A - Ahi)
__device__ __align__(16) signed char g_A8h[(size_t)B_ROWS * K_DIM];  // quant(Ahi)
__device__ __align__(16) signed char g_W8h[(size_t)N_DIM * K_DIM];   // quant(Whi)
__device__ __align__(16) signed char g_W8l[(size_t)N_DIM * K_DIM];   // quant(W - Whi)
__device__ float g_sAl[B_ROWS];
__device__ float g_sAh[B_ROWS];
__device__ float g_sWh[N_DIM];
__device__ float g_sWl[N_DIM];

// ---------------- PTX helpers (base sm_103 target only) ---------------------
__device__ __forceinline__ uint32_t smem_u32(const void* p) {
    uint32_t a;
    asm("{ .reg .u64 t; cvta.to.shared.u64 t, %1; cvt.u32.u64 %0, t; }" : "=r"(a) : "l"(p));
    return a;
}
#define CP_ASYNC16(dst, src) \
    asm volatile("cp.async.cg.shared.global [%0], [%1], 16;" :: "r"(dst), "l"(src))
#define CP_COMMIT() asm volatile("cp.async.commit_group;")
#define CP_WAIT2()  asm volatile("cp.async.wait_group 2;")
#define LDMX4(r0, r1, r2, r3, addr) \
    asm volatile("ldmatrix.sync.aligned.m8n8.x4.shared.b16 {%0,%1,%2,%3}, [%4];" \
        : "=r"(r0), "=r"(r1), "=r"(r2), "=r"(r3) : "r"(addr))
#define MMA_BF16(d, a, b) \
    asm volatile("mma.sync.aligned.m16n8k16.row.col.f32.bf16.bf16.f32 " \
        "{%0,%1,%2,%3}, {%4,%5,%6,%7}, {%8,%9}, {%0,%1,%2,%3};" \
        : "+f"((d)[0]), "+f"((d)[1]), "+f"((d)[2]), "+f"((d)[3]) \
        : "r"((a)[0]), "r"((a)[1]), "r"((a)[2]), "r"((a)[3]), "r"((b)[0]), "r"((b)[1]))
#define MMA_S8(d, a, b) \
    asm volatile("mma.sync.aligned.m16n8k32.row.col.s32.s8.s8.s32 " \
        "{%0,%1,%2,%3}, {%4,%5,%6,%7}, {%8,%9}, {%0,%1,%2,%3};" \
        : "+r"((d)[0]), "+r"((d)[1]), "+r"((d)[2]), "+r"((d)[3]) \
        : "r"((a)[0]), "r"((a)[1]), "r"((a)[2]), "r"((a)[3]), "r"((b)[0]), "r"((b)[1]))

// ---------------- kernel 0: split + int8 quantization (one warp per row) ----
// hi = bf16(x); q_lo = int8 quant of (x - hi) with per-row scale; q_hi = int8
// quant of hi with per-row scale. Scales stored as max/127.
__global__ __launch_bounds__(256)
void split_quant(const float* __restrict__ src, __nv_bfloat16* __restrict__ hi,
                 signed char* __restrict__ ql, signed char* __restrict__ qh,
                 float* __restrict__ sl, float* __restrict__ sh, int nrows) {
    const int gw   = (blockIdx.x * 256 + threadIdx.x) >> 5;
    const int lane = threadIdx.x & 31;
    if (gw >= nrows) return;
    const size_t base = (size_t)gw * K_DIM;

    float hf[16], rf[16];
    float mr = 0.f, mh = 0.f;
    #pragma unroll
    for (int i = 0; i < 16; i++) {
        float v = src[base + lane + 32 * i];
        __nv_bfloat16 hb = __float2bfloat16_rn(v);
        float h = __bfloat162float(hb);
        hi[base + lane + 32 * i] = hb;
        hf[i] = h;
        rf[i] = v - h;
        mr = fmaxf(mr, fabsf(rf[i]));
        mh = fmaxf(mh, fabsf(h));
    }
    #pragma unroll
    for (int o = 16; o; o >>= 1) {
        mr = fmaxf(mr, __shfl_xor_sync(0xffffffffu, mr, o));
        mh = fmaxf(mh, __shfl_xor_sync(0xffffffffu, mh, o));
    }
    const float il = (mr > 0.f) ? 127.f / mr : 0.f;
    const float ih = (mh > 0.f) ? 127.f / mh : 0.f;
    #pragma unroll
    for (int i = 0; i < 16; i++) {
        ql[base + lane + 32 * i] = (signed char)__float2int_rn(rf[i] * il);
        qh[base + lane + 32 * i] = (signed char)__float2int_rn(hf[i] * ih);
    }
    if (lane == 0) {
        sl[gw] = mr * (1.f / 127.f);
        sh[gw] = mh * (1.f / 127.f);
    }
}

// ---------------- kernel 1: hybrid GEMM  Y = A @ W^T ------------------------
// Term 0 (iters 0-7):  bf16 Ah x Wh, k64/stage, fp32 MMA accum.
// Term 1 (iters 8-11): int8 quant(A-Ah) x quant(Wh), k128/stage, s32 accum.
// Term 2 (iters 12-15): int8 quant(Ah) x quant(W-Wh), k128/stage, s32 accum.
// Each int8 term dequantized once (per-row scales) into the fp32 accumulators.
// Every stage is 128 rows x 128 bytes for both operands; substep = 32B
// (k16 bf16 / k32 int8) so ldmatrix addressing is identical in all passes.
#define STAGES      4
#define PITCH       144                  // 128B data + 16B pad (odd*16B => conflict-free)
#define A_ST        (128 * PITCH)        // 18432 B
#define ST_BYTES    (2 * A_ST)           // 36864 B
#define GEMM_SMEM   (STAGES * ST_BYTES)  // 147456 B
#define NITER       16

__global__ __launch_bounds__(256, 1)
void gemm_mma() {
    extern __shared__ char sm[];
    const int tid  = threadIdx.x;
    const int lane = tid & 31;
    const int warp = tid >> 5;
    const int bm = blockIdx.y * 128;
    const int bn = blockIdx.x * 128;
    const int wm = (warp >> 2) * 64;
    const int wn = (warp & 3) * 32;

    const uint32_t sbase = smem_u32(sm);

    float accf[4][4][4];
    int   accs[4][4][4];
    #pragma unroll
    for (int i = 0; i < 4; i++)
        #pragma unroll
        for (int j = 0; j < 4; j++)
            #pragma unroll
            for (int r = 0; r < 4; r++) { accf[i][j][r] = 0.f; accs[i][j][r] = 0; }

    const uint32_t a_off = (uint32_t)(wm + (lane & 15)) * PITCH + ((lane >> 4) & 1) * 16;
    const uint32_t b_off = A_ST +
        (uint32_t)(wn + (lane & 7) + ((lane >> 4) & 1) * 8) * PITCH + ((lane >> 3) & 1) * 16;

    auto load_stage = [&](int iter, int stage) {
        const char* Ab;
        const char* Bb;
        size_t rs;
        if (iter < 8) {          // bf16: row stride 1024B, k-offset iter*64 elem = 128B
            Ab = (const char*)g_Ahi + (size_t)iter * 128;
            Bb = (const char*)g_Whi + (size_t)iter * 128;
            rs = 1024;
        } else if (iter < 12) {  // int8: row stride 512B, k-offset (iter-8)*128B
            Ab = (const char*)g_A8l + (size_t)(iter - 8) * 128;
            Bb = (const char*)g_W8h + (size_t)(iter - 8) * 128;
            rs = 512;
        } else {
            Ab = (const char*)g_A8h + (size_t)(iter - 12) * 128;
            Bb = (const char*)g_W8l + (size_t)(iter - 12) * 128;
            rs = 512;
        }
        const uint32_t as = sbase + stage * ST_BYTES;
        const uint32_t bs = as + A_ST;
        #pragma unroll
        for (int j = 0; j < 4; j++) {
            const int i   = tid + j * 256;   // 0..1023
            const int row = i >> 3;
            const int c   = i & 7;
            CP_ASYNC16(as + row * PITCH + c * 16, Ab + (size_t)(bm + row) * rs + c * 16);
        }
        #pragma unroll
        for (int j = 0; j < 4; j++) {
            const int i   = tid + j * 256;
            const int row = i >> 3;
            const int c   = i & 7;
            CP_ASYNC16(bs + row * PITCH + c * 16, Bb + (size_t)(bn + row) * rs + c * 16);
        }
        CP_COMMIT();
    };

    load_stage(0, 0);
    load_stage(1, 1);
    load_stage(2, 2);

    #pragma unroll 1
    for (int iter = 0; iter < NITER; iter++) {
        const int stage = iter & 3;
        CP_WAIT2();
        __syncthreads();
        if (iter + 3 < NITER) load_stage(iter + 3, (iter + 3) & 3);
        else                  CP_COMMIT();   // keep wait-group count uniform

        const uint32_t as = sbase + stage * ST_BYTES;
        const bool isbf = (iter < 8);
        #pragma unroll
        for (int s = 0; s < 4; s++) {
            uint32_t af[4][4];
            #pragma unroll
            for (int mf = 0; mf < 4; mf++)
                LDMX4(af[mf][0], af[mf][1], af[mf][2], af[mf][3],
                      as + a_off + mf * 16 * PITCH + s * 32);
            uint32_t bfr[4][2];
            #pragma unroll
            for (int p = 0; p < 2; p++) {
                uint32_t r0, r1, r2, r3;
                LDMX4(r0, r1, r2, r3, as + b_off + p * 16 * PITCH + s * 32);
                bfr[2 * p][0] = r0;     bfr[2 * p][1] = r1;
                bfr[2 * p + 1][0] = r2; bfr[2 * p + 1][1] = r3;
            }
            if (isbf) {
                #pragma unroll
                for (int mf = 0; mf < 4; mf++)
                    #pragma unroll
                    for (int nf = 0; nf < 4; nf++)
                        MMA_BF16(accf[mf][nf], af[mf], bfr[nf]);
            } else {
                #pragma unroll
                for (int mf = 0; mf < 4; mf++)
                    #pragma unroll
                    for (int nf = 0; nf < 4; nf++)
                        MMA_S8(accs[mf][nf], af[mf], bfr[nf]);
            }
        }

        if (iter == 11 || iter == 15) {      // dequantize int8 term into accf
            const float* sA = (iter == 11) ? g_sAl : g_sAh;
            const float* sW = (iter == 11) ? g_sWh : g_sWl;
            float fa0[4], fa1[4], fb0[4], fb1[4];
            #pragma unroll
            for (int mf = 0; mf < 4; mf++) {
                const int r = bm + wm + mf * 16 + (lane >> 2);
                fa0[mf] = sA[r];
                fa1[mf] = sA[r + 8];
            }
            #pragma unroll
            for (int nf = 0; nf < 4; nf++) {
                const int c = bn + wn + nf * 8 + (lane & 3) * 2;
                fb0[nf] = sW[c];
                fb1[nf] = sW[c + 1];
            }
            #pragma unroll
            for (int mf = 0; mf < 4; mf++)
                #pragma unroll
                for (int nf = 0; nf < 4; nf++) {
                    accf[mf][nf][0] = fmaf((float)accs[mf][nf][0], fa0[mf] * fb0[nf], accf[mf][nf][0]);
                    accf[mf][nf][1] = fmaf((float)accs[mf][nf][1], fa0[mf] * fb1[nf], accf[mf][nf][1]);
                    accf[mf][nf][2] = fmaf((float)accs[mf][nf][2], fa1[mf] * fb0[nf], accf[mf][nf][2]);
                    accf[mf][nf][3] = fmaf((float)accs[mf][nf][3], fa1[mf] * fb1[nf], accf[mf][nf][3]);
                    accs[mf][nf][0] = 0; accs[mf][nf][1] = 0;
                    accs[mf][nf][2] = 0; accs[mf][nf][3] = 0;
                }
        }
    }

    // epilogue: fragment layout -> g_Y
    #pragma unroll
    for (int mf = 0; mf < 4; mf++) {
        const int gm = bm + wm + mf * 16 + (lane >> 2);
        #pragma unroll
        for (int nf = 0; nf < 4; nf++) {
            const int gn = bn + wn + nf * 8 + (lane & 3) * 2;
            *(float2*)(g_Y + (size_t)gm * N_DIM + gn)       = make_float2(accf[mf][nf][0], accf[mf][nf][1]);
            *(float2*)(g_Y + (size_t)(gm + 8) * N_DIM + gn) = make_float2(accf[mf][nf][2], accf[mf][nf][3]);
        }
    }
}

// ---------------- kernel 2: GhostBatchNorm stats (fold gamma/beta) ----------
__global__ __launch_bounds__(256)
void bn_stats(const float* __restrict__ gamma, const float* __restrict__ beta) {
    const int d  = blockIdx.x * 256 + threadIdx.x;
    const int vb = blockIdx.y;
    const float* p = g_Y + (size_t)vb * VBS * N_DIM + d;
    float s = 0.f, s2 = 0.f;
    #pragma unroll 8
    for (int r = 0; r < VBS; r++) {
        float v = p[(size_t)r * N_DIM];
        s += v;
        s2 = fmaf(v, v, s2);
    }
    float mean = s * (1.f / VBS);
    float var  = s2 * (1.f / VBS) - mean * mean;
    float sc   = gamma[d] * rsqrtf(var + 1e-5f);
    g_scale[vb * N_DIM + d] = sc;
    g_shift[vb * N_DIM + d] = fmaf(-mean, sc, beta[d]);
}

// ---------------- kernel 3: fused BN-apply + prior + exact sparsemax --------
__global__ __launch_bounds__(256)
void sparsemax_fused(const float* __restrict__ priors, float* __restrict__ out) {
    const int row = blockIdx.x;
    const int vb  = row >> 8;
    const int t   = threadIdx.x;
    const int c0  = t * 8;

    __shared__ float warp_s[8];
    __shared__ float warp_c[8];
    __shared__ float bcast[2];

    const float* yrow = g_Y     + (size_t)row * N_DIM;
    const float* prow = priors  + (size_t)row * N_DIM;
    const float* scr  = g_scale + (size_t)vb * N_DIM;
    const float* shr  = g_shift + (size_t)vb * N_DIM;

    float z[8];
    #pragma unroll
    for (int v = 0; v < 2; v++) {
        float4 y  = *(const float4*)(yrow + c0 + v * 4);
        float4 p  = *(const float4*)(prow + c0 + v * 4);
        float4 sc = *(const float4*)(scr  + c0 + v * 4);
        float4 sh = *(const float4*)(shr  + c0 + v * 4);
        z[v * 4 + 0] = fmaf(y.x, sc.x, sh.x) * p.x;
        z[v * 4 + 1] = fmaf(y.y, sc.y, sh.y) * p.y;
        z[v * 4 + 2] = fmaf(y.z, sc.z, sh.z) * p.z;
        z[v * 4 + 3] = fmaf(y.w, sc.w, sh.w) * p.w;
    }

    float ls = 0.f, lc = 0.f;
    #pragma unroll
    for (int i = 0; i < 8; i++) ls += z[i];
    #pragma unroll
    for (int o = 16; o; o >>= 1) ls += __shfl_down_sync(0xffffffffu, ls, o);
    if ((t & 31) == 0) warp_s[t >> 5] = ls;
    __syncthreads();
    if (t < 32) {
        float s = (t < 8) ? warp_s[t] : 0.f;
        #pragma unroll
        for (int o = 4; o; o >>= 1) s += __shfl_down_sync(0xffffffffu, s, o);
        if (t == 0) bcast[0] = s;
    }
    __syncthreads();
    float tau   = (bcast[0] - 1.f) * (1.f / (float)N_DIM);
    float kprev = (float)N_DIM;
    __syncthreads();

    for (int it = 0; it < 64; it++) {
        ls = 0.f; lc = 0.f;
        #pragma unroll
        for (int i = 0; i < 8; i++)
            if (z[i] > tau) { ls += z[i]; lc += 1.f; }
        #pragma unroll
        for (int o = 16; o; o >>= 1) {
            ls += __shfl_down_sync(0xffffffffu, ls, o);
            lc += __shfl_down_sync(0xffffffffu, lc, o);
        }
        if ((t & 31) == 0) { warp_s[t >> 5] = ls; warp_c[t >> 5] = lc; }
        __syncthreads();
        if (t < 32) {
            float s = (t < 8) ? warp_s[t] : 0.f;
            float c = (t < 8) ? warp_c[t] : 0.f;
            #pragma unroll
            for (int o = 4; o; o >>= 1) {
                s += __shfl_down_sync(0xffffffffu, s, o);
                c += __shfl_down_sync(0xffffffffu, c, o);
            }
            if (t == 0) { bcast[0] = s; bcast[1] = c; }
        }
        __syncthreads();
        float S = bcast[0];
        float C = bcast[1];
        __syncthreads();
        if (C == kprev) break;
        tau   = (S - 1.f) / C;
        kprev = C;
    }

    float o0[8];
    #pragma unroll
    for (int i = 0; i < 8; i++) o0[i] = fmaxf(z[i] - tau, 0.f);
    float* orow = out + (size_t)row * N_DIM + c0;
    *(float4*)(orow)     = make_float4(o0[0], o0[1], o0[2], o0[3]);
    *(float4*)(orow + 4) = make_float4(o0[4], o0[5], o0[6], o0[7]);
}

// ---------------- host side --------------------------------------------------
extern "C" void kernel_launch(void* const* d_in, const int* in_sizes, int n_in,
                              void* d_out, int out_size) {
    const float* priors = (const float*)d_in[0];
    const float* feat   = (const float*)d_in[1];
    const float* W      = (const float*)d_in[2];
    const float* gamma  = (const float*)d_in[3];
    const float* beta   = (const float*)d_in[4];
    float* out = (float*)d_out;

    void *pAhi, *pWhi, *pA8l, *pA8h, *pW8h, *pW8l, *psAl, *psAh, *psWh, *psWl;
    cudaGetSymbolAddress(&pAhi, g_Ahi);
    cudaGetSymbolAddress(&pWhi, g_Whi);
    cudaGetSymbolAddress(&pA8l, g_A8l);
    cudaGetSymbolAddress(&pA8h, g_A8h);
    cudaGetSymbolAddress(&pW8h, g_W8h);
    cudaGetSymbolAddress(&pW8l, g_W8l);
    cudaGetSymbolAddress(&psAl, g_sAl);
    cudaGetSymbolAddress(&psAh, g_sAh);
    cudaGetSymbolAddress(&psWh, g_sWh);
    cudaGetSymbolAddress(&psWl, g_sWl);

    cudaFuncSetAttribute(gemm_mma, cudaFuncAttributeMaxDynamicSharedMemorySize, GEMM_SMEM);

    // split + quantize (8 rows per 256-thread block)
    split_quant<<<B_ROWS / 8, 256>>>(feat, (__nv_bfloat16*)pAhi, (signed char*)pA8l,
                                     (signed char*)pA8h, (float*)psAl, (float*)psAh, B_ROWS);
    split_quant<<<N_DIM / 8, 256>>>(W, (__nv_bfloat16*)pWhi, (signed char*)pW8l,
                                    (signed char*)pW8h, (float*)psWl, (float*)psWh, N_DIM);

    // hybrid bf16 + int8-correction GEMM
    dim3 ggrid(N_DIM / 128, B_ROWS / 128);   // (16, 256)
    gemm_mma<<<ggrid, 256, GEMM_SMEM>>>();

    // BN stats + fused epilogue
    dim3 sgrid(N_DIM / 256, NVB);
    bn_stats<<<sgrid, 256>>>(gamma, beta);
    sparsemax_fused<<<B_ROWS, 256>>>(priors, out);
}

// round 17
// speedup vs baseline: 1.0012x; 1.0012x over previous
#include <cuda_runtime.h>
#include <cuda_bf16.h>
#include <cstdint>

#define B_ROWS 32768
#define K_DIM  512
#define N_DIM  2048
#define VBS    256
#define NVB    128

// ---------------- scratch (device globals; no allocations allowed) ----------
__device__ __align__(16) float g_Y[(size_t)B_ROWS * N_DIM];
__device__ __align__(16) float g_scale[NVB * N_DIM];
__device__ __align__(16) float g_shift[NVB * N_DIM];
__device__ __align__(16) __nv_bfloat16 g_Ahi[(size_t)B_ROWS * K_DIM];
__device__ __align__(16) __nv_bfloat16 g_Whi[(size_t)N_DIM * K_DIM];
__device__ __align__(16) signed char g_A8l[(size_t)B_ROWS * K_DIM];  // quant(A - Ahi)
__device__ __align__(16) signed char g_A8h[(size_t)B_ROWS * K_DIM];  // quant(Ahi)
__device__ __align__(16) signed char g_W8h[(size_t)N_DIM * K_DIM];   // quant(Whi)
__device__ __align__(16) signed char g_W8l[(size_t)N_DIM * K_DIM];   // quant(W - Whi)
__device__ float g_sAl[B_ROWS];
__device__ float g_sAh[B_ROWS];
__device__ float g_sWh[N_DIM];
__device__ float g_sWl[N_DIM];

// ---------------- PTX helpers (base sm_103 target only) ---------------------
__device__ __forceinline__ uint32_t smem_u32(const void* p) {
    uint32_t a;
    asm("{ .reg .u64 t; cvta.to.shared.u64 t, %1; cvt.u32.u64 %0, t; }" : "=r"(a) : "l"(p));
    return a;
}
#define CP_ASYNC16(dst, src) \
    asm volatile("cp.async.cg.shared.global [%0], [%1], 16;" :: "r"(dst), "l"(src))
#define CP_COMMIT() asm volatile("cp.async.commit_group;")
#define CP_WAIT2()  asm volatile("cp.async.wait_group 2;")
#define LDMX4(r0, r1, r2, r3, addr) \
    asm volatile("ldmatrix.sync.aligned.m8n8.x4.shared.b16 {%0,%1,%2,%3}, [%4];" \
        : "=r"(r0), "=r"(r1), "=r"(r2), "=r"(r3) : "r"(addr))
#define MMA_BF16(d, a, b) \
    asm volatile("mma.sync.aligned.m16n8k16.row.col.f32.bf16.bf16.f32 " \
        "{%0,%1,%2,%3}, {%4,%5,%6,%7}, {%8,%9}, {%0,%1,%2,%3};" \
        : "+f"((d)[0]), "+f"((d)[1]), "+f"((d)[2]), "+f"((d)[3]) \
        : "r"((a)[0]), "r"((a)[1]), "r"((a)[2]), "r"((a)[3]), "r"((b)[0]), "r"((b)[1]))
#define MMA_S8(d, a, b) \
    asm volatile("mma.sync.aligned.m16n8k32.row.col.s32.s8.s8.s32 " \
        "{%0,%1,%2,%3}, {%4,%5,%6,%7}, {%8,%9}, {%0,%1,%2,%3};" \
        : "+r"((d)[0]), "+r"((d)[1]), "+r"((d)[2]), "+r"((d)[3]) \
        : "r"((a)[0]), "r"((a)[1]), "r"((a)[2]), "r"((a)[3]), "r"((b)[0]), "r"((b)[1]))

// ---------------- kernel 0: split + int8 quantization (one warp per row) ----
// hi = bf16(x); q_lo = int8 quant of (x - hi) with per-row scale; q_hi = int8
// quant of hi with per-row scale. Scales stored as max/127.
__global__ __launch_bounds__(256)
void split_quant(const float* __restrict__ src, __nv_bfloat16* __restrict__ hi,
                 signed char* __restrict__ ql, signed char* __restrict__ qh,
                 float* __restrict__ sl, float* __restrict__ sh, int nrows) {
    const int gw   = (blockIdx.x * 256 + threadIdx.x) >> 5;
    const int lane = threadIdx.x & 31;
    if (gw >= nrows) return;
    const size_t base = (size_t)gw * K_DIM;

    float hf[16], rf[16];
    float mr = 0.f, mh = 0.f;
    #pragma unroll
    for (int i = 0; i < 16; i++) {
        float v = src[base + lane + 32 * i];
        __nv_bfloat16 hb = __float2bfloat16_rn(v);
        float h = __bfloat162float(hb);
        hi[base + lane + 32 * i] = hb;
        hf[i] = h;
        rf[i] = v - h;
        mr = fmaxf(mr, fabsf(rf[i]));
        mh = fmaxf(mh, fabsf(h));
    }
    #pragma unroll
    for (int o = 16; o; o >>= 1) {
        mr = fmaxf(mr, __shfl_xor_sync(0xffffffffu, mr, o));
        mh = fmaxf(mh, __shfl_xor_sync(0xffffffffu, mh, o));
    }
    const float il = (mr > 0.f) ? 127.f / mr : 0.f;
    const float ih = (mh > 0.f) ? 127.f / mh : 0.f;
    #pragma unroll
    for (int i = 0; i < 16; i++) {
        ql[base + lane + 32 * i] = (signed char)__float2int_rn(rf[i] * il);
        qh[base + lane + 32 * i] = (signed char)__float2int_rn(hf[i] * ih);
    }
    if (lane == 0) {
        sl[gw] = mr * (1.f / 127.f);
        sh[gw] = mh * (1.f / 127.f);
    }
}

// ---------------- kernel 1: hybrid GEMM  Y = A @ W^T ------------------------
// Term 0 (iters 0-7):  bf16 Ah x Wh, k64/stage, fp32 MMA accum.
// Term 1 (iters 8-11): int8 quant(A-Ah) x quant(Wh), k128/stage, s32 accum.
// Term 2 (iters 12-15): int8 quant(Ah) x quant(W-Wh), k128/stage, s32 accum.
// Each int8 term dequantized once (per-row scales) into the fp32 accumulators.
// Every stage is 128 rows x 128 bytes for both operands; substep = 32B
// (k16 bf16 / k32 int8) so ldmatrix addressing is identical in all passes.
#define STAGES      4
#define PITCH       144                  // 128B data + 16B pad (odd*16B => conflict-free)
#define A_ST        (128 * PITCH)        // 18432 B
#define ST_BYTES    (2 * A_ST)           // 36864 B
#define GEMM_SMEM   (STAGES * ST_BYTES)  // 147456 B
#define NITER       16

__global__ __launch_bounds__(256, 1)
void gemm_mma() {
    extern __shared__ char sm[];
    const int tid  = threadIdx.x;
    const int lane = tid & 31;
    const int warp = tid >> 5;
    const int bm = blockIdx.y * 128;
    const int bn = blockIdx.x * 128;
    const int wm = (warp >> 2) * 64;
    const int wn = (warp & 3) * 32;

    const uint32_t sbase = smem_u32(sm);

    float accf[4][4][4];
    int   accs[4][4][4];
    #pragma unroll
    for (int i = 0; i < 4; i++)
        #pragma unroll
        for (int j = 0; j < 4; j++)
            #pragma unroll
            for (int r = 0; r < 4; r++) { accf[i][j][r] = 0.f; accs[i][j][r] = 0; }

    const uint32_t a_off = (uint32_t)(wm + (lane & 15)) * PITCH + ((lane >> 4) & 1) * 16;
    const uint32_t b_off = A_ST +
        (uint32_t)(wn + (lane & 7) + ((lane >> 4) & 1) * 8) * PITCH + ((lane >> 3) & 1) * 16;

    auto load_stage = [&](int iter, int stage) {
        const char* Ab;
        const char* Bb;
        size_t rs;
        if (iter < 8) {          // bf16: row stride 1024B, k-offset iter*64 elem = 128B
            Ab = (const char*)g_Ahi + (size_t)iter * 128;
            Bb = (const char*)g_Whi + (size_t)iter * 128;
            rs = 1024;
        } else if (iter < 12) {  // int8: row stride 512B, k-offset (iter-8)*128B
            Ab = (const char*)g_A8l + (size_t)(iter - 8) * 128;
            Bb = (const char*)g_W8h + (size_t)(iter - 8) * 128;
            rs = 512;
        } else {
            Ab = (const char*)g_A8h + (size_t)(iter - 12) * 128;
            Bb = (const char*)g_W8l + (size_t)(iter - 12) * 128;
            rs = 512;
        }
        const uint32_t as = sbase + stage * ST_BYTES;
        const uint32_t bs = as + A_ST;
        #pragma unroll
        for (int j = 0; j < 4; j++) {
            const int i   = tid + j * 256;   // 0..1023
            const int row = i >> 3;
            const int c   = i & 7;
            CP_ASYNC16(as + row * PITCH + c * 16, Ab + (size_t)(bm + row) * rs + c * 16);
        }
        #pragma unroll
        for (int j = 0; j < 4; j++) {
            const int i   = tid + j * 256;
            const int row = i >> 3;
            const int c   = i & 7;
            CP_ASYNC16(bs + row * PITCH + c * 16, Bb + (size_t)(bn + row) * rs + c * 16);
        }
        CP_COMMIT();
    };

    load_stage(0, 0);
    load_stage(1, 1);
    load_stage(2, 2);

    #pragma unroll 1
    for (int iter = 0; iter < NITER; iter++) {
        const int stage = iter & 3;
        CP_WAIT2();
        __syncthreads();
        if (iter + 3 < NITER) load_stage(iter + 3, (iter + 3) & 3);
        else                  CP_COMMIT();   // keep wait-group count uniform

        const uint32_t as = sbase + stage * ST_BYTES;
        const bool isbf = (iter < 8);
        #pragma unroll
        for (int s = 0; s < 4; s++) {
            uint32_t af[4][4];
            #pragma unroll
            for (int mf = 0; mf < 4; mf++)
                LDMX4(af[mf][0], af[mf][1], af[mf][2], af[mf][3],
                      as + a_off + mf * 16 * PITCH + s * 32);
            uint32_t bfr[4][2];
            #pragma unroll
            for (int p = 0; p < 2; p++) {
                uint32_t r0, r1, r2, r3;
                LDMX4(r0, r1, r2, r3, as + b_off + p * 16 * PITCH + s * 32);
                bfr[2 * p][0] = r0;     bfr[2 * p][1] = r1;
                bfr[2 * p + 1][0] = r2; bfr[2 * p + 1][1] = r3;
            }
            if (isbf) {
                #pragma unroll
                for (int mf = 0; mf < 4; mf++)
                    #pragma unroll
                    for (int nf = 0; nf < 4; nf++)
                        MMA_BF16(accf[mf][nf], af[mf], bfr[nf]);
            } else {
                #pragma unroll
                for (int mf = 0; mf < 4; mf++)
                    #pragma unroll
                    for (int nf = 0; nf < 4; nf++)
                        MMA_S8(accs[mf][nf], af[mf], bfr[nf]);
            }
        }

        if (iter == 11 || iter == 15) {      // dequantize int8 term into accf
            const float* sA = (iter == 11) ? g_sAl : g_sAh;
            const float* sW = (iter == 11) ? g_sWh : g_sWl;
            float fa0[4], fa1[4], fb0[4], fb1[4];
            #pragma unroll
            for (int mf = 0; mf < 4; mf++) {
                const int r = bm + wm + mf * 16 + (lane >> 2);
                fa0[mf] = sA[r];
                fa1[mf] = sA[r + 8];
            }
            #pragma unroll
            for (int nf = 0; nf < 4; nf++) {
                const int c = bn + wn + nf * 8 + (lane & 3) * 2;
                fb0[nf] = sW[c];
                fb1[nf] = sW[c + 1];
            }
            #pragma unroll
            for (int mf = 0; mf < 4; mf++)
                #pragma unroll
                for (int nf = 0; nf < 4; nf++) {
                    accf[mf][nf][0] = fmaf((float)accs[mf][nf][0], fa0[mf] * fb0[nf], accf[mf][nf][0]);
                    accf[mf][nf][1] = fmaf((float)accs[mf][nf][1], fa0[mf] * fb1[nf], accf[mf][nf][1]);
                    accf[mf][nf][2] = fmaf((float)accs[mf][nf][2], fa1[mf] * fb0[nf], accf[mf][nf][2]);
                    accf[mf][nf][3] = fmaf((float)accs[mf][nf][3], fa1[mf] * fb1[nf], accf[mf][nf][3]);
                    accs[mf][nf][0] = 0; accs[mf][nf][1] = 0;
                    accs[mf][nf][2] = 0; accs[mf][nf][3] = 0;
                }
        }
    }

    // epilogue: fragment layout -> g_Y
    #pragma unroll
    for (int mf = 0; mf < 4; mf++) {
        const int gm = bm + wm + mf * 16 + (lane >> 2);
        #pragma unroll
        for (int nf = 0; nf < 4; nf++) {
            const int gn = bn + wn + nf * 8 + (lane & 3) * 2;
            *(float2*)(g_Y + (size_t)gm * N_DIM + gn)       = make_float2(accf[mf][nf][0], accf[mf][nf][1]);
            *(float2*)(g_Y + (size_t)(gm + 8) * N_DIM + gn) = make_float2(accf[mf][nf][2], accf[mf][nf][3]);
        }
    }
}

// ---------------- kernel 2: GhostBatchNorm stats (fold gamma/beta) ----------
__global__ __launch_bounds__(256)
void bn_stats(const float* __restrict__ gamma, const float* __restrict__ beta) {
    const int d  = blockIdx.x * 256 + threadIdx.x;
    const int vb = blockIdx.y;
    const float* p = g_Y + (size_t)vb * VBS * N_DIM + d;
    float s = 0.f, s2 = 0.f;
    #pragma unroll 8
    for (int r = 0; r < VBS; r++) {
        float v = p[(size_t)r * N_DIM];
        s += v;
        s2 = fmaf(v, v, s2);
    }
    float mean = s * (1.f / VBS);
    float var  = s2 * (1.f / VBS) - mean * mean;
    float sc   = gamma[d] * rsqrtf(var + 1e-5f);
    g_scale[vb * N_DIM + d] = sc;
    g_shift[vb * N_DIM + d] = fmaf(-mean, sc, beta[d]);
}

// ---------------- kernel 3: fused BN-apply + prior + exact sparsemax --------
__global__ __launch_bounds__(256)
void sparsemax_fused(const float* __restrict__ priors, float* __restrict__ out) {
    const int row = blockIdx.x;
    const int vb  = row >> 8;
    const int t   = threadIdx.x;
    const int c0  = t * 8;

    __shared__ float warp_s[8];
    __shared__ float warp_c[8];
    __shared__ float bcast[2];

    const float* yrow = g_Y     + (size_t)row * N_DIM;
    const float* prow = priors  + (size_t)row * N_DIM;
    const float* scr  = g_scale + (size_t)vb * N_DIM;
    const float* shr  = g_shift + (size_t)vb * N_DIM;

    float z[8];
    #pragma unroll
    for (int v = 0; v < 2; v++) {
        float4 y  = *(const float4*)(yrow + c0 + v * 4);
        float4 p  = *(const float4*)(prow + c0 + v * 4);
        float4 sc = *(const float4*)(scr  + c0 + v * 4);
        float4 sh = *(const float4*)(shr  + c0 + v * 4);
        z[v * 4 + 0] = fmaf(y.x, sc.x, sh.x) * p.x;
        z[v * 4 + 1] = fmaf(y.y, sc.y, sh.y) * p.y;
        z[v * 4 + 2] = fmaf(y.z, sc.z, sh.z) * p.z;
        z[v * 4 + 3] = fmaf(y.w, sc.w, sh.w) * p.w;
    }

    float ls = 0.f, lc = 0.f;
    #pragma unroll
    for (int i = 0; i < 8; i++) ls += z[i];
    #pragma unroll
    for (int o = 16; o; o >>= 1) ls += __shfl_down_sync(0xffffffffu, ls, o);
    if ((t & 31) == 0) warp_s[t >> 5] = ls;
    __syncthreads();
    if (t < 32) {
        float s = (t < 8) ? warp_s[t] : 0.f;
        #pragma unroll
        for (int o = 4; o; o >>= 1) s += __shfl_down_sync(0xffffffffu, s, o);
        if (t == 0) bcast[0] = s;
    }
    __syncthreads();
    float tau   = (bcast[0] - 1.f) * (1.f / (float)N_DIM);
    float kprev = (float)N_DIM;
    __syncthreads();

    for (int it = 0; it < 64; it++) {
        ls = 0.f; lc = 0.f;
        #pragma unroll
        for (int i = 0; i < 8; i++)
            if (z[i] > tau) { ls += z[i]; lc += 1.f; }
        #pragma unroll
        for (int o = 16; o; o >>= 1) {
            ls += __shfl_down_sync(0xffffffffu, ls, o);
            lc += __shfl_down_sync(0xffffffffu, lc, o);
        }
        if ((t & 31) == 0) { warp_s[t >> 5] = ls; warp_c[t >> 5] = lc; }
        __syncthreads();
        if (t < 32) {
            float s = (t < 8) ? warp_s[t] : 0.f;
            float c = (t < 8) ? warp_c[t] : 0.f;
            #pragma unroll
            for (int o = 4; o; o >>= 1) {
                s += __shfl_down_sync(0xffffffffu, s, o);
                c += __shfl_down_sync(0xffffffffu, c, o);
            }
            if (t == 0) { bcast[0] = s; bcast[1] = c; }
        }
        __syncthreads();
        float S = bcast[0];
        float C = bcast[1];
        __syncthreads();
        if (C == kprev) break;
        tau   = (S - 1.f) / C;
        kprev = C;
    }

    float o0[8];
    #pragma unroll
    for (int i = 0; i < 8; i++) o0[i] = fmaxf(z[i] - tau, 0.f);
    float* orow = out + (size_t)row * N_DIM + c0;
    *(float4*)(orow)     = make_float4(o0[0], o0[1], o0[2], o0[3]);
    *(float4*)(orow + 4) = make_float4(o0[4], o0[5], o0[6], o0[7]);
}

// ---------------- host side --------------------------------------------------
extern "C" void kernel_launch(void* const* d_in, const int* in_sizes, int n_in,
                              void* d_out, int out_size) {
    const float* priors = (const float*)d_in[0];
    const float* feat   = (const float*)d_in[1];
    const float* W      = (const float*)d_in[2];
    const float* gamma  = (const float*)d_in[3];
    const float* beta   = (const float*)d_in[4];
    float* out = (float*)d_out;

    void *pAhi, *pWhi, *pA8l, *pA8h, *pW8h, *pW8l, *psAl, *psAh, *psWh, *psWl;
    cudaGetSymbolAddress(&pAhi, g_Ahi);
    cudaGetSymbolAddress(&pWhi, g_Whi);
    cudaGetSymbolAddress(&pA8l, g_A8l);
    cudaGetSymbolAddress(&pA8h, g_A8h);
    cudaGetSymbolAddress(&pW8h, g_W8h);
    cudaGetSymbolAddress(&pW8l, g_W8l);
    cudaGetSymbolAddress(&psAl, g_sAl);
    cudaGetSymbolAddress(&psAh, g_sAh);
    cudaGetSymbolAddress(&psWh, g_sWh);
    cudaGetSymbolAddress(&psWl, g_sWl);

    cudaFuncSetAttribute(gemm_mma, cudaFuncAttributeMaxDynamicSharedMemorySize, GEMM_SMEM);

    // split + quantize (8 rows per 256-thread block)
    split_quant<<<B_ROWS / 8, 256>>>(feat, (__nv_bfloat16*)pAhi, (signed char*)pA8l,
                                     (signed char*)pA8h, (float*)psAl, (float*)psAh, B_ROWS);
    split_quant<<<N_DIM / 8, 256>>>(W, (__nv_bfloat16*)pWhi, (signed char*)pW8l,
                                    (signed char*)pW8h, (float*)psWl, (float*)psWh, N_DIM);

    // hybrid bf16 + int8-correction GEMM
    dim3 ggrid(N_DIM / 128, B_ROWS / 128);   // (16, 256)
    gemm_mma<<<ggrid, 256, GEMM_SMEM>>>();

    // BN stats + fused epilogue
    dim3 sgrid(N_DIM / 256, NVB);
    bn_stats<<<sgrid, 256>>>(gamma, beta);
    sparsemax_fused<<<B_ROWS, 256>>>(priors, out);
}